// round 8
// baseline (speedup 1.0000x reference)
#include <cuda_runtime.h>
#include <math.h>

#define UNITS 1024
#define FEAT  1024
#define GCOLS 4096                  // 4 * UNITS gate columns
#define CTILE 128                   // columns per block (32 lanes x float4)
#define NCB   (GCOLS / CTILE)       // 32 column tiles
#define KS    4                     // k-slices
#define NBLK  (NCB * KS)            // 128 blocks (all co-resident on 148 SMs)
#define KROWS (FEAT / KS)           // 256 k-rows per block
#define WARPS 32                    // warps per block (1024 threads)
#define KPW   (KROWS / WARPS)       // 8 k-rows per warp

// Scratch (device globals)
__device__ float4 g_p0[KS][GCOLS / 4];   // partials of x0@W (per k-slice)
__device__ float4 g_p1[KS][GCOLS / 4];   // partials of x1@W
__device__ float4 g_pu[KS][GCOLS / 4];   // partials of h0@U

// Replay-safe grid barrier state (zero-initialized). count returns to 0 after
// each use; gen increments monotonically -> safe across graph replays.
__device__ unsigned g_bar_count[2];
__device__ unsigned g_bar_gen[2];

__device__ __forceinline__ float sigmoidf_(float x) {
    return 1.0f / (1.0f + expf(-x));
}

__device__ __forceinline__ void grid_barrier(int id) {
    __syncthreads();
    if (threadIdx.x == 0) {
        const unsigned gen = *(volatile unsigned*)&g_bar_gen[id];
        __threadfence();
        const unsigned t = atomicAdd(&g_bar_count[id], 1u);
        if (t == NBLK - 1) {
            g_bar_count[id] = 0;
            __threadfence();
            atomicAdd(&g_bar_gen[id], 1u);
        } else {
            while (*(volatile unsigned*)&g_bar_gen[id] == gen) { }
        }
        __threadfence();
    }
    __syncthreads();
}

// Fold the KS partials of a gate column (fixed order) — scalar view.
__device__ __forceinline__ float fold_p(const float4 (*p)[GCOLS / 4], int col) {
    const float* base = reinterpret_cast<const float*>(p);
    float s = 0.f;
    #pragma unroll
    for (int sI = 0; sI < KS; ++sI) s += base[sI * GCOLS + col];
    return s;
}

// ---------------------------------------------------------------------------
// Single fused persistent kernel. 128 blocks x 1024 threads.
// Block (cb, ks): columns [cb*128, cb*128+128), k-rows [ks*256, ks*256+256).
// Phase A: W sweep (t0 & t1 partials) -> barrier
// Phase B: reconstruct h0 slice, U sweep -> barrier
// Phase C: block 0: gate math t0/t1, dense head, finite diff, 4 outputs.
// ---------------------------------------------------------------------------
__global__ void __launch_bounds__(1024, 1)
k_fused(const float* __restrict__ x, const float* __restrict__ W,
        const float* __restrict__ U, const float* __restrict__ b,
        const float* __restrict__ f, const float* __restrict__ Wd,
        const float* __restrict__ bd, float* __restrict__ out) {
    __shared__ float  xs0[KROWS], xs1[KROWS];
    __shared__ float4 sred0[WARPS][32];
    __shared__ float4 sred1[WARPS][32];
    __shared__ float  red[4][32];

    const int tid  = threadIdx.x;
    const int lane = tid & 31;
    const int r    = tid >> 5;
    const int cb   = blockIdx.x & (NCB - 1);
    const int ks   = blockIdx.x >> 5;
    const int colv = cb * 32 + lane;            // float4-column index
    const int kbase = ks * KROWS;

    // ---- Phase A: x@W partials for t=0 and t=1 ----
    for (int i = tid; i < KROWS; i += 1024) {
        xs0[i] = x[kbase + i];
        xs1[i] = x[FEAT + kbase + i];
    }
    __syncthreads();

    {
        const float4* Wp = reinterpret_cast<const float4*>(W)
                         + (size_t)(kbase + r * KPW) * (GCOLS / 4) + colv;
        float4 a0 = make_float4(0.f, 0.f, 0.f, 0.f);
        float4 a1 = make_float4(0.f, 0.f, 0.f, 0.f);
        #pragma unroll
        for (int kk = 0; kk < KPW; ++kk) {
            const float4 w = Wp[(size_t)kk * (GCOLS / 4)];
            const float xa = xs0[r * KPW + kk];
            const float xb = xs1[r * KPW + kk];
            a0.x = fmaf(xa, w.x, a0.x); a0.y = fmaf(xa, w.y, a0.y);
            a0.z = fmaf(xa, w.z, a0.z); a0.w = fmaf(xa, w.w, a0.w);
            a1.x = fmaf(xb, w.x, a1.x); a1.y = fmaf(xb, w.y, a1.y);
            a1.z = fmaf(xb, w.z, a1.z); a1.w = fmaf(xb, w.w, a1.w);
        }
        sred0[r][lane] = a0;
        sred1[r][lane] = a1;
    }
    __syncthreads();

    if (tid < 32) {
        float4 s0 = make_float4(0.f, 0.f, 0.f, 0.f);
        #pragma unroll
        for (int rr = 0; rr < WARPS; ++rr) {
            const float4 v = sred0[rr][tid];
            s0.x += v.x; s0.y += v.y; s0.z += v.z; s0.w += v.w;
        }
        g_p0[ks][cb * 32 + tid] = s0;
        __threadfence();
    } else if (tid < 64) {
        const int c = tid - 32;
        float4 s1 = make_float4(0.f, 0.f, 0.f, 0.f);
        #pragma unroll
        for (int rr = 0; rr < WARPS; ++rr) {
            const float4 v = sred1[rr][c];
            s1.x += v.x; s1.y += v.y; s1.z += v.z; s1.w += v.w;
        }
        g_p1[ks][cb * 32 + c] = s1;
        __threadfence();
    }

    grid_barrier(0);

    // ---- Phase B: reconstruct h0 slice, then h0@U partials ----
    // reuse xs0 as h0 slice storage
    if (tid < KROWS) {
        const int u = kbase + tid;
        const float zi = fold_p(g_p0, u)             + __ldg(b + u);
        const float zg = fold_p(g_p0, 2 * UNITS + u) + __ldg(b + 2 * UNITS + u);
        const float zo = fold_p(g_p0, 3 * UNITS + u) + __ldg(b + 3 * UNITS + u);
        const float c0 = sigmoidf_(zi) * zg;
        xs0[tid] = sigmoidf_(zo) * c0;
    }
    __syncthreads();

    {
        const float4* Up = reinterpret_cast<const float4*>(U)
                         + (size_t)(kbase + r * KPW) * (GCOLS / 4) + colv;
        float4 a = make_float4(0.f, 0.f, 0.f, 0.f);
        #pragma unroll
        for (int kk = 0; kk < KPW; ++kk) {
            const float4 w = Up[(size_t)kk * (GCOLS / 4)];
            const float h = xs0[r * KPW + kk];
            a.x = fmaf(h, w.x, a.x); a.y = fmaf(h, w.y, a.y);
            a.z = fmaf(h, w.z, a.z); a.w = fmaf(h, w.w, a.w);
        }
        sred0[r][lane] = a;
    }
    __syncthreads();

    if (tid < 32) {
        float4 s = make_float4(0.f, 0.f, 0.f, 0.f);
        #pragma unroll
        for (int rr = 0; rr < WARPS; ++rr) {
            const float4 v = sred0[rr][tid];
            s.x += v.x; s.y += v.y; s.z += v.z; s.w += v.w;
        }
        g_pu[ks][cb * 32 + tid] = s;
        __threadfence();
    }

    grid_barrier(1);

    // ---- Phase C: block 0 finishes ----
    if (blockIdx.x != 0) return;

    const int u = tid;   // 1024 threads = UNITS

    const float zi0 = fold_p(g_p0, u)             + __ldg(b + u);
    const float zg0 = fold_p(g_p0, 2 * UNITS + u) + __ldg(b + 2 * UNITS + u);
    const float zo0 = fold_p(g_p0, 3 * UNITS + u) + __ldg(b + 3 * UNITS + u);
    const float c0  = sigmoidf_(zi0) * zg0;
    const float h0  = sigmoidf_(zo0) * c0;

    const float zi1 = fold_p(g_p1, u)             + fold_p(g_pu, u)             + __ldg(b + u);
    const float zf1 = fold_p(g_p1, UNITS + u)     + fold_p(g_pu, UNITS + u)     + __ldg(b + UNITS + u);
    const float zg1 = fold_p(g_p1, 2 * UNITS + u) + fold_p(g_pu, 2 * UNITS + u) + __ldg(b + 2 * UNITS + u);
    const float zo1 = fold_p(g_p1, 3 * UNITS + u) + fold_p(g_pu, 3 * UNITS + u) + __ldg(b + 3 * UNITS + u);
    const float c1  = sigmoidf_(zf1) * c0 + sigmoidf_(zi1) * zg1;
    const float h1  = sigmoidf_(zo1) * c1;

    const float n0 = tanhf(h0);
    const float n1 = tanhf(h1);

    const float wd0 = __ldg(Wd + 2 * u);
    const float wd1 = __ldg(Wd + 2 * u + 1);
    float v0 = n0 * wd0;   // -> h_c[0,0]
    float v1 = n0 * wd1;   // -> h_c[0,1]
    float v2 = n1 * wd0;   // -> h_c[1,0]
    float v3 = n1 * wd1;   // -> h_c[1,1]

    const unsigned m = 0xffffffffu;
    #pragma unroll
    for (int off = 16; off > 0; off >>= 1) {
        v0 += __shfl_down_sync(m, v0, off);
        v1 += __shfl_down_sync(m, v1, off);
        v2 += __shfl_down_sync(m, v2, off);
        v3 += __shfl_down_sync(m, v3, off);
    }
    if (lane == 0) {
        red[0][r] = v0; red[1][r] = v1; red[2][r] = v2; red[3][r] = v3;
    }
    __syncthreads();

    if (r == 0) {
        float r0 = red[0][lane];
        float r1 = red[1][lane];
        float r2 = red[2][lane];
        float r3 = red[3][lane];
        #pragma unroll
        for (int off = 16; off > 0; off >>= 1) {
            r0 += __shfl_down_sync(m, r0, off);
            r1 += __shfl_down_sync(m, r1, off);
            r2 += __shfl_down_sync(m, r2, off);
            r3 += __shfl_down_sync(m, r3, off);
        }
        if (lane == 0) {
            const float b0 = __ldg(bd + 0);
            const float b1 = __ldg(bd + 1);
            const float hc00 = tanhf(r0 + b0);   // h_c[0,0]
            const float hc01 = tanhf(r1 + b1);   // h_c[0,1]
            const float hc10 = tanhf(r2 + b0);   // h_c[1,0]
            const float hc11 = tanhf(r3 + b1);   // h_c[1,1]
            const float den  = __ldg(f + 1) - __ldg(f + 2);
            out[0] = hc00;                       // h_out
            out[1] = hc01;
            out[2] = (hc00 - hc10) / den;        // H
            out[3] = (hc01 - hc11) / den;
        }
    }
}

// ---------------------------------------------------------------------------
extern "C" void kernel_launch(void* const* d_in, const int* in_sizes, int n_in,
                              void* d_out, int out_size) {
    (void)in_sizes; (void)n_in; (void)out_size;
    const float* x  = (const float*)d_in[0];   // inputs (1, 8192, 1024)
    const float* f  = (const float*)d_in[1];   // f (8192, 1)
    const float* W  = (const float*)d_in[2];   // (1024, 4096)
    const float* U  = (const float*)d_in[3];   // (1024, 4096)
    const float* b  = (const float*)d_in[4];   // (4096,)
    const float* Wd = (const float*)d_in[5];   // (1024, 2)
    const float* bd = (const float*)d_in[6];   // (2,)
    float* out = (float*)d_out;

    k_fused<<<NBLK, 1024>>>(x, W, U, b, f, Wd, bd, out);
}

// round 9
// speedup vs baseline: 1.1186x; 1.1186x over previous
#include <cuda_runtime.h>
#include <math.h>

#define UNITS 1024
#define FEAT  1024
#define GCOLS 4096                  // 4 * UNITS gate columns
#define CTILE 128                   // columns per block (32 lanes x float4)
#define NCB   (GCOLS / CTILE)       // 32 column tiles
#define KS    4                     // k-slices
#define KROWS (FEAT / KS)           // 256 k-rows per block
#define WARPS 32                    // warps per block (1024 threads)
#define KPW   (KROWS / WARPS)       // 8 k-rows per warp

#define WTILE_FLOATS (KROWS * CTILE)        // 32768 floats = 128KB
#define SMEM_XW (WTILE_FLOATS*4 + 2*KROWS*4 + 2*WARPS*32*16)   // 165,888 B
#define SMEM_HU (WTILE_FLOATS*4 +   KROWS*4 +   WARPS*32*16)   // 148,480 B

// Scratch (device globals)
__device__ float4 g_p0[KS][GCOLS / 4];   // partials of x0@W (per k-slice)
__device__ float4 g_p1[KS][GCOLS / 4];   // partials of x1@W
__device__ float4 g_pu[KS][GCOLS / 4];   // partials of h0@U

__device__ __forceinline__ float sigmoidf_(float x) {
    return 1.0f / (1.0f + expf(-x));
}

__device__ __forceinline__ void cp_async16(void* sptr, const void* gptr) {
    unsigned saddr = (unsigned)__cvta_generic_to_shared(sptr);
    asm volatile("cp.async.cg.shared.global [%0], [%1], 16;\n"
                 :: "r"(saddr), "l"(gptr));
}
__device__ __forceinline__ void cp_async_commit_wait() {
    asm volatile("cp.async.commit_group;\n" ::);
    asm volatile("cp.async.wait_group 0;\n" ::);
}

// Fold the KS partials of a gate column (fixed order) — scalar view.
__device__ __forceinline__ float fold_p(const float4 (*p)[GCOLS / 4], int col) {
    const float* base = reinterpret_cast<const float*>(p);
    float s = 0.f;
    #pragma unroll
    for (int sI = 0; sI < KS; ++sI) s += base[sI * GCOLS + col];
    return s;
}

// ---------------------------------------------------------------------------
// Kernel 1: partial GEMV over W for timesteps 0 and 1.
// grid = (NCB, KS) = (32, 4) = 128 blocks x 1024 threads.
// Block (cb, ks): columns [cb*128, cb*128+128), k in [ks*256, ks*256+256).
// The full 128KB W tile is staged into shared via cp.async (8 x 16B per
// thread, all in flight -> BW-limited fill), then consumed from shared.
// ---------------------------------------------------------------------------
__global__ void __launch_bounds__(1024, 1)
k_xw(const float* __restrict__ x, const float* __restrict__ W) {
    extern __shared__ char dyn[];
    float*  Wt   = (float*)dyn;                              // [KROWS][CTILE]
    float*  xs0  = (float*)(dyn + WTILE_FLOATS * 4);
    float*  xs1  = xs0 + KROWS;
    float4* sred0 = (float4*)(xs1 + KROWS);                  // [WARPS][32]
    float4* sred1 = sred0 + WARPS * 32;

    const int tid  = threadIdx.x;
    const int lane = tid & 31;
    const int r    = tid >> 5;
    const int cb   = blockIdx.x;
    const int ks   = blockIdx.y;
    const int kbase = ks * KROWS;

    // stage W tile: 8192 float4 ops, 8 per thread, row-contiguous
    const float* gW = W + (size_t)kbase * GCOLS + cb * CTILE;
    #pragma unroll
    for (int i = 0; i < 8; ++i) {
        const int idx = tid + i * 1024;      // 0..8191
        const int row = idx >> 5;
        const int c   = idx & 31;
        cp_async16(Wt + row * CTILE + c * 4,
                   gW + (size_t)row * GCOLS + c * 4);
    }
    // x slices via regular loads (tiny)
    for (int i = tid; i < KROWS; i += 1024) {
        xs0[i] = x[kbase + i];
        xs1[i] = x[FEAT + kbase + i];
    }
    cp_async_commit_wait();
    __syncthreads();

    // consume from shared: warp r -> k-rows r*8..r*8+7, lane -> float4 col
    float4 a0 = make_float4(0.f, 0.f, 0.f, 0.f);
    float4 a1 = make_float4(0.f, 0.f, 0.f, 0.f);
    #pragma unroll
    for (int kk = 0; kk < KPW; ++kk) {
        const int row = r * KPW + kk;
        const float4 w = reinterpret_cast<const float4*>(Wt + row * CTILE)[lane];
        const float xa = xs0[row];
        const float xb = xs1[row];
        a0.x = fmaf(xa, w.x, a0.x); a0.y = fmaf(xa, w.y, a0.y);
        a0.z = fmaf(xa, w.z, a0.z); a0.w = fmaf(xa, w.w, a0.w);
        a1.x = fmaf(xb, w.x, a1.x); a1.y = fmaf(xb, w.y, a1.y);
        a1.z = fmaf(xb, w.z, a1.z); a1.w = fmaf(xb, w.w, a1.w);
    }
    sred0[r * 32 + lane] = a0;
    sred1[r * 32 + lane] = a1;
    __syncthreads();

    if (tid < 32) {
        float4 s0 = make_float4(0.f, 0.f, 0.f, 0.f);
        #pragma unroll
        for (int rr = 0; rr < WARPS; ++rr) {
            const float4 v = sred0[rr * 32 + tid];
            s0.x += v.x; s0.y += v.y; s0.z += v.z; s0.w += v.w;
        }
        g_p0[ks][cb * 32 + tid] = s0;
    } else if (tid < 64) {
        const int c = tid - 32;
        float4 s1 = make_float4(0.f, 0.f, 0.f, 0.f);
        #pragma unroll
        for (int rr = 0; rr < WARPS; ++rr) {
            const float4 v = sred1[rr * 32 + c];
            s1.x += v.x; s1.y += v.y; s1.z += v.z; s1.w += v.w;
        }
        g_p1[ks][cb * 32 + c] = s1;
    }
}

// ---------------------------------------------------------------------------
// Kernel 2: partial GEMV over U. Same staging; each block reconstructs the
// 256 h0 values it needs from the x@W partials (+b) first (c_prev = 0).
// ---------------------------------------------------------------------------
__global__ void __launch_bounds__(1024, 1)
k_hu(const float* __restrict__ U, const float* __restrict__ b) {
    extern __shared__ char dyn[];
    float*  Ut   = (float*)dyn;                              // [KROWS][CTILE]
    float*  h0s  = (float*)(dyn + WTILE_FLOATS * 4);
    float4* sred = (float4*)(h0s + KROWS);                   // [WARPS][32]

    const int tid  = threadIdx.x;
    const int lane = tid & 31;
    const int r    = tid >> 5;
    const int cb   = blockIdx.x;
    const int ks   = blockIdx.y;
    const int kbase = ks * KROWS;

    const float* gU = U + (size_t)kbase * GCOLS + cb * CTILE;
    #pragma unroll
    for (int i = 0; i < 8; ++i) {
        const int idx = tid + i * 1024;
        const int row = idx >> 5;
        const int c   = idx & 31;
        cp_async16(Ut + row * CTILE + c * 4,
                   gU + (size_t)row * GCOLS + c * 4);
    }
    // reconstruct h0 slice while the tile streams in
    if (tid < KROWS) {
        const int u = kbase + tid;
        const float zi = fold_p(g_p0, u)             + __ldg(b + u);
        const float zg = fold_p(g_p0, 2 * UNITS + u) + __ldg(b + 2 * UNITS + u);
        const float zo = fold_p(g_p0, 3 * UNITS + u) + __ldg(b + 3 * UNITS + u);
        const float c0 = sigmoidf_(zi) * zg;
        h0s[tid] = sigmoidf_(zo) * c0;
    }
    cp_async_commit_wait();
    __syncthreads();

    float4 a = make_float4(0.f, 0.f, 0.f, 0.f);
    #pragma unroll
    for (int kk = 0; kk < KPW; ++kk) {
        const int row = r * KPW + kk;
        const float4 w = reinterpret_cast<const float4*>(Ut + row * CTILE)[lane];
        const float h = h0s[row];
        a.x = fmaf(h, w.x, a.x); a.y = fmaf(h, w.y, a.y);
        a.z = fmaf(h, w.z, a.z); a.w = fmaf(h, w.w, a.w);
    }
    sred[r * 32 + lane] = a;
    __syncthreads();

    if (tid < 32) {
        float4 s = make_float4(0.f, 0.f, 0.f, 0.f);
        #pragma unroll
        for (int rr = 0; rr < WARPS; ++rr) {
            const float4 v = sred[rr * 32 + tid];
            s.x += v.x; s.y += v.y; s.z += v.z; s.w += v.w;
        }
        g_pu[ks][cb * 32 + tid] = s;
    }
}

// ---------------------------------------------------------------------------
// Kernel 3: one block, 1024 threads = UNITS. Fold all partials, gate math for
// t=0 and t=1, dense head via deterministic in-block reduction, finite diff.
// ---------------------------------------------------------------------------
__global__ void k_final(const float* __restrict__ f,
                        const float* __restrict__ b,
                        const float* __restrict__ Wd,
                        const float* __restrict__ bd,
                        float* __restrict__ out) {
    __shared__ float red[4][32];
    const int u = threadIdx.x;   // 0..1023

    const float zi0 = fold_p(g_p0, u)             + __ldg(b + u);
    const float zg0 = fold_p(g_p0, 2 * UNITS + u) + __ldg(b + 2 * UNITS + u);
    const float zo0 = fold_p(g_p0, 3 * UNITS + u) + __ldg(b + 3 * UNITS + u);
    const float c0  = sigmoidf_(zi0) * zg0;
    const float h0  = sigmoidf_(zo0) * c0;

    const float zi1 = fold_p(g_p1, u)             + fold_p(g_pu, u)             + __ldg(b + u);
    const float zf1 = fold_p(g_p1, UNITS + u)     + fold_p(g_pu, UNITS + u)     + __ldg(b + UNITS + u);
    const float zg1 = fold_p(g_p1, 2 * UNITS + u) + fold_p(g_pu, 2 * UNITS + u) + __ldg(b + 2 * UNITS + u);
    const float zo1 = fold_p(g_p1, 3 * UNITS + u) + fold_p(g_pu, 3 * UNITS + u) + __ldg(b + 3 * UNITS + u);
    const float c1  = sigmoidf_(zf1) * c0 + sigmoidf_(zi1) * zg1;
    const float h1  = sigmoidf_(zo1) * c1;

    const float n0 = tanhf(h0);
    const float n1 = tanhf(h1);

    const float wd0 = __ldg(Wd + 2 * u);
    const float wd1 = __ldg(Wd + 2 * u + 1);
    float v0 = n0 * wd0;   // -> h_c[0,0]
    float v1 = n0 * wd1;   // -> h_c[0,1]
    float v2 = n1 * wd0;   // -> h_c[1,0]
    float v3 = n1 * wd1;   // -> h_c[1,1]

    const unsigned m = 0xffffffffu;
    const int lane = u & 31;
    const int wrp  = u >> 5;
    #pragma unroll
    for (int off = 16; off > 0; off >>= 1) {
        v0 += __shfl_down_sync(m, v0, off);
        v1 += __shfl_down_sync(m, v1, off);
        v2 += __shfl_down_sync(m, v2, off);
        v3 += __shfl_down_sync(m, v3, off);
    }
    if (lane == 0) {
        red[0][wrp] = v0; red[1][wrp] = v1; red[2][wrp] = v2; red[3][wrp] = v3;
    }
    __syncthreads();

    if (wrp == 0) {
        float r0 = red[0][lane];
        float r1 = red[1][lane];
        float r2 = red[2][lane];
        float r3 = red[3][lane];
        #pragma unroll
        for (int off = 16; off > 0; off >>= 1) {
            r0 += __shfl_down_sync(m, r0, off);
            r1 += __shfl_down_sync(m, r1, off);
            r2 += __shfl_down_sync(m, r2, off);
            r3 += __shfl_down_sync(m, r3, off);
        }
        if (lane == 0) {
            const float b0 = __ldg(bd + 0);
            const float b1 = __ldg(bd + 1);
            const float hc00 = tanhf(r0 + b0);   // h_c[0,0]
            const float hc01 = tanhf(r1 + b1);   // h_c[0,1]
            const float hc10 = tanhf(r2 + b0);   // h_c[1,0]
            const float hc11 = tanhf(r3 + b1);   // h_c[1,1]
            const float den  = __ldg(f + 1) - __ldg(f + 2);
            out[0] = hc00;                       // h_out
            out[1] = hc01;
            out[2] = (hc00 - hc10) / den;        // H
            out[3] = (hc01 - hc11) / den;
        }
    }
}

// ---------------------------------------------------------------------------
extern "C" void kernel_launch(void* const* d_in, const int* in_sizes, int n_in,
                              void* d_out, int out_size) {
    (void)in_sizes; (void)n_in; (void)out_size;
    const float* x  = (const float*)d_in[0];   // inputs (1, 8192, 1024)
    const float* f  = (const float*)d_in[1];   // f (8192, 1)
    const float* W  = (const float*)d_in[2];   // (1024, 4096)
    const float* U  = (const float*)d_in[3];   // (1024, 4096)
    const float* b  = (const float*)d_in[4];   // (4096,)
    const float* Wd = (const float*)d_in[5];   // (1024, 2)
    const float* bd = (const float*)d_in[6];   // (2,)
    float* out = (float*)d_out;

    cudaFuncSetAttribute(k_xw, cudaFuncAttributeMaxDynamicSharedMemorySize, SMEM_XW);
    cudaFuncSetAttribute(k_hu, cudaFuncAttributeMaxDynamicSharedMemorySize, SMEM_HU);

    dim3 grid(NCB, KS);   // (32, 4) = 128 blocks
    k_xw   <<<grid, 1024, SMEM_XW>>>(x, W);
    k_hu   <<<grid, 1024, SMEM_HU>>>(U, b);
    k_final<<<1, 1024>>>(f, b, Wd, bd, out);
}